// round 12
// baseline (speedup 1.0000x reference)
#include <cuda_runtime.h>
#include <cstdint>

// ---------------------------------------------------------------------------
// ChamferLoss via uniform-grid exact nearest neighbor.
//   32^3 grid over each set's exact bbox; counting sort; ring expansion with
//   exact termination: after finishing Chebyshev ring R, all unvisited points
//   are >= (R-1)*h_min away, so stop when best <= (R-1)*h_min.
// Typical query: ring 0+1 = 27 cells, ~100 point evals (vs 16384 brute force).
// ---------------------------------------------------------------------------

#define NMAX   16384
#define GRIDC  32
#define NCELL  (GRIDC * GRIDC * GRIDC)
#define SCAN_T 1024
#define CPT    (NCELL / SCAN_T)        // 32 cells per scan thread

// scratch (static device arrays; no allocations)
__device__ float4   g_pts[2][NMAX];
__device__ float4   g_sorted[2][NMAX];
__device__ int      g_cellid[2][NMAX];
__device__ int      g_cnt[2][NCELL];
__device__ int      g_start[2][NCELL + 1];
__device__ int      g_cursor[2][NCELL];
__device__ unsigned g_bbox[2][6];      // encoded: min x,y,z ; max x,y,z

// monotonic float<->uint encoding for atomicMin/Max over signed floats
__device__ __forceinline__ unsigned enc(float f) {
    unsigned u = __float_as_uint(f);
    return (u & 0x80000000u) ? ~u : (u | 0x80000000u);
}
__device__ __forceinline__ float dec(unsigned e) {
    unsigned u = (e & 0x80000000u) ? (e & 0x7FFFFFFFu) : ~e;
    return __uint_as_float(u);
}

__device__ __forceinline__ void grid_params(int s, float3& bmin, float3& inv_h,
                                            float& hmin) {
    float x0 = dec(g_bbox[s][0]), y0 = dec(g_bbox[s][1]), z0 = dec(g_bbox[s][2]);
    float x1 = dec(g_bbox[s][3]), y1 = dec(g_bbox[s][4]), z1 = dec(g_bbox[s][5]);
    float sx = fmaxf(x1 - x0, 1e-6f), sy = fmaxf(y1 - y0, 1e-6f),
          sz = fmaxf(z1 - z0, 1e-6f);
    bmin = make_float3(x0, y0, z0);
    inv_h = make_float3((float)GRIDC / sx, (float)GRIDC / sy, (float)GRIDC / sz);
    hmin = fminf(sx, fminf(sy, sz)) * (1.0f / (float)GRIDC);
}

__device__ __forceinline__ int cell_clamp(float v, float b, float ih) {
    int c = (int)floorf((v - b) * ih);
    return min(GRIDC - 1, max(0, c));
}

// ---------------------------------------------------------------------------
__global__ void init_kernel(float* out) {
    int i = blockIdx.x * blockDim.x + threadIdx.x;
    if (i == 0) {
        *out = 0.0f;
        #pragma unroll
        for (int s = 0; s < 2; s++) {
            g_bbox[s][0] = g_bbox[s][1] = g_bbox[s][2] = 0xFFFFFFFFu;
            g_bbox[s][3] = g_bbox[s][4] = g_bbox[s][5] = 0u;
        }
    }
    if (i < NCELL) { g_cnt[0][i] = 0; g_cnt[1][i] = 0; }
}

// ---------------------------------------------------------------------------
__global__ void prep_kernel(const float* __restrict__ tgt,
                            const float* __restrict__ outp, int n, int m) {
    int i = blockIdx.x * blockDim.x + threadIdx.x;
    if (i < n) {
        float x = tgt[3 * i], y = tgt[3 * i + 1], z = tgt[3 * i + 2];
        g_pts[0][i] = make_float4(x, y, z, 0.f);
        atomicMin(&g_bbox[0][0], enc(x)); atomicMax(&g_bbox[0][3], enc(x));
        atomicMin(&g_bbox[0][1], enc(y)); atomicMax(&g_bbox[0][4], enc(y));
        atomicMin(&g_bbox[0][2], enc(z)); atomicMax(&g_bbox[0][5], enc(z));
    }
    if (i < m) {
        float x = outp[3 * i], y = outp[3 * i + 1], z = outp[3 * i + 2];
        g_pts[1][i] = make_float4(x, y, z, 0.f);
        atomicMin(&g_bbox[1][0], enc(x)); atomicMax(&g_bbox[1][3], enc(x));
        atomicMin(&g_bbox[1][1], enc(y)); atomicMax(&g_bbox[1][4], enc(y));
        atomicMin(&g_bbox[1][2], enc(z)); atomicMax(&g_bbox[1][5], enc(z));
    }
}

// ---------------------------------------------------------------------------
__global__ void count_kernel(int n, int m) {
    int i = blockIdx.x * blockDim.x + threadIdx.x;
    #pragma unroll
    for (int s = 0; s < 2; s++) {
        int cnt = (s == 0) ? n : m;
        if (i < cnt) {
            float3 bmin, ih; float hmin;
            grid_params(s, bmin, ih, hmin);
            float4 p = g_pts[s][i];
            int cx = cell_clamp(p.x, bmin.x, ih.x);
            int cy = cell_clamp(p.y, bmin.y, ih.y);
            int cz = cell_clamp(p.z, bmin.z, ih.z);
            int c = (cz * GRIDC + cy) * GRIDC + cx;
            g_cellid[s][i] = c;
            atomicAdd(&g_cnt[s][c], 1);
        }
    }
}

// ---------------------------------------------------------------------------
__global__ __launch_bounds__(SCAN_T) void scan_kernel() {
    __shared__ int partial[SCAN_T];
    const int s = blockIdx.x;
    const int t = threadIdx.x;
    const int base = t * CPT;

    int total = 0;
    #pragma unroll
    for (int i = 0; i < CPT; i++) total += g_cnt[s][base + i];
    partial[t] = total;
    __syncthreads();
    for (int off = 1; off < SCAN_T; off <<= 1) {
        int v = (t >= off) ? partial[t - off] : 0;
        __syncthreads();
        partial[t] += v;
        __syncthreads();
    }
    int run = (t > 0) ? partial[t - 1] : 0;   // exclusive prefix
    #pragma unroll
    for (int i = 0; i < CPT; i++) {
        g_start[s][base + i] = run;
        g_cursor[s][base + i] = run;
        run += g_cnt[s][base + i];
    }
    if (t == SCAN_T - 1) g_start[s][NCELL] = run;
}

// ---------------------------------------------------------------------------
__global__ void scatter_kernel(int n, int m) {
    int i = blockIdx.x * blockDim.x + threadIdx.x;
    #pragma unroll
    for (int s = 0; s < 2; s++) {
        int cnt = (s == 0) ? n : m;
        if (i < cnt) {
            int c = g_cellid[s][i];
            int pos = atomicAdd(&g_cursor[s][c], 1);
            g_sorted[s][pos] = g_pts[s][i];
        }
    }
}

// ---------------------------------------------------------------------------
__global__ __launch_bounds__(256) void query_kernel(int n, int m, float* out) {
    __shared__ float warp_sums[8];
    const int gi = blockIdx.x * blockDim.x + threadIdx.x;
    const int total = n + m;

    float dist = 0.0f;
    if (gi < total) {
        const int s = (gi < n) ? 0 : 1;        // query set
        const int r = 1 - s;                   // ref set
        const int qi = (s == 0) ? gi : gi - n;
        const float4 q = g_sorted[s][qi];      // sorted order: warp-coherent cells

        float3 bmin, ih; float hmin;
        grid_params(r, bmin, ih, hmin);
        const int cx = cell_clamp(q.x, bmin.x, ih.x);
        const int cy = cell_clamp(q.y, bmin.y, ih.y);
        const int cz = cell_clamp(q.z, bmin.z, ih.z);

        float best2 = 3.4e38f;
        for (int R = 0; R <= GRIDC; R++) {
            if (R > 0) {
                float lb = (float)(R - 1) * hmin;
                if (best2 <= lb * lb) break;   // exact: unvisited >= (R-1)*hmin
            }
            int zlo = max(cz - R, 0), zhi = min(cz + R, GRIDC - 1);
            for (int z = zlo; z <= zhi; z++) {
                bool zface = (z == cz - R) || (z == cz + R);
                int ylo = max(cy - R, 0), yhi = min(cy + R, GRIDC - 1);
                for (int y = ylo; y <= yhi; y++) {
                    bool yface = (y == cy - R) || (y == cy + R);
                    int xlo, xhi, xstep;
                    if (zface || yface) {
                        xlo = max(cx - R, 0); xhi = min(cx + R, GRIDC - 1); xstep = 1;
                    } else {
                        xlo = cx - R; xhi = cx + R; xstep = 2 * R;  // faces only
                    }
                    int rowbase = (z * GRIDC + y) * GRIDC;
                    for (int x = xlo; x <= xhi; x += xstep) {
                        if (x < 0 || x >= GRIDC) continue;
                        int c = rowbase + x;
                        int p0 = g_start[r][c], p1 = g_start[r][c + 1];
                        for (int p = p0; p < p1; p++) {
                            float4 b = g_sorted[r][p];
                            float dx = q.x - b.x, dy = q.y - b.y, dz = q.z - b.z;
                            float d2 = fmaf(dx, dx, fmaf(dy, dy, dz * dz));
                            best2 = fminf(best2, d2);
                        }
                    }
                }
            }
        }
        dist = sqrtf(best2);
    }

    // block reduction -> single atomicAdd
    #pragma unroll
    for (int o = 16; o > 0; o >>= 1)
        dist += __shfl_down_sync(0xFFFFFFFFu, dist, o);
    int lane = threadIdx.x & 31, wid = threadIdx.x >> 5;
    if (lane == 0) warp_sums[wid] = dist;
    __syncthreads();
    if (wid == 0) {
        dist = (lane < 8) ? warp_sums[lane] : 0.0f;
        #pragma unroll
        for (int o = 4; o > 0; o >>= 1)
            dist += __shfl_down_sync(0xFFFFFFFFu, dist, o);
        if (lane == 0) atomicAdd(out, dist * 1.0e-3f);
    }
}

// ---------------------------------------------------------------------------
extern "C" void kernel_launch(void* const* d_in, const int* in_sizes, int n_in,
                              void* d_out, int out_size) {
    const float* target = (const float*)d_in[0];
    const float* output = (const float*)d_in[1];
    const int n = in_sizes[0] / 3;
    const int m = in_sizes[1] / 3;
    float* out = (float*)d_out;

    int pmax = max(n, m);
    init_kernel<<<(NCELL + 255) / 256, 256>>>(out);
    prep_kernel<<<(pmax + 255) / 256, 256>>>(target, output, n, m);
    count_kernel<<<(pmax + 255) / 256, 256>>>(n, m);
    scan_kernel<<<2, SCAN_T>>>();
    scatter_kernel<<<(pmax + 255) / 256, 256>>>(n, m);
    query_kernel<<<(n + m + 255) / 256, 256>>>(n, m, out);
}

// round 17
// speedup vs baseline: 2.4641x; 2.4641x over previous
#include <cuda_runtime.h>
#include <cstdint>

// ---------------------------------------------------------------------------
// ChamferLoss via uniform-grid exact NN — parallel execution shape.
//  Phase A: 8 lanes per query scan rings 0-1 (27 cells) with lane-striped,
//           coalesced candidate loads. Done iff best2 <= hmin^2 (exact).
//  Phase B: warp per unfinished query walks shells R=2.. cooperatively.
//  Scan replaced by atomic segment-offset assignment (order-free).
// ---------------------------------------------------------------------------

#define NMAX  16384
#define GRIDC 32
#define NCELL (GRIDC * GRIDC * GRIDC)

__device__ float4   g_pts[2][NMAX];
__device__ float4   g_sorted[2][NMAX];
__device__ int      g_cellid[2][NMAX];
__device__ int      g_cnt[2][NCELL];
__device__ int2     g_seg[2][NCELL];     // (start, count)
__device__ int      g_cursor[2][NCELL];
__device__ int      g_total[2];
__device__ unsigned g_bbox[2][6];
__device__ float    g_best2[2 * NMAX];
__device__ int      g_ovf[2 * NMAX];
__device__ int      g_ovfcnt;

__device__ __forceinline__ unsigned enc(float f) {
    unsigned u = __float_as_uint(f);
    return (u & 0x80000000u) ? ~u : (u | 0x80000000u);
}
__device__ __forceinline__ float dec(unsigned e) {
    unsigned u = (e & 0x80000000u) ? (e & 0x7FFFFFFFu) : ~e;
    return __uint_as_float(u);
}
__device__ __forceinline__ void grid_params(int s, float3& bmin, float3& ih,
                                            float& hmin) {
    float x0 = dec(g_bbox[s][0]), y0 = dec(g_bbox[s][1]), z0 = dec(g_bbox[s][2]);
    float x1 = dec(g_bbox[s][3]), y1 = dec(g_bbox[s][4]), z1 = dec(g_bbox[s][5]);
    float sx = fmaxf(x1 - x0, 1e-6f), sy = fmaxf(y1 - y0, 1e-6f),
          sz = fmaxf(z1 - z0, 1e-6f);
    bmin = make_float3(x0, y0, z0);
    ih = make_float3((float)GRIDC / sx, (float)GRIDC / sy, (float)GRIDC / sz);
    hmin = fminf(sx, fminf(sy, sz)) * (1.0f / (float)GRIDC);
}
__device__ __forceinline__ int cell_clamp(float v, float b, float ihv) {
    int c = (int)floorf((v - b) * ihv);
    return min(GRIDC - 1, max(0, c));
}
__device__ __forceinline__ void scan_cell(int r, int c, float4 q, float& best2) {
    int2 seg = g_seg[r][c];
    for (int p = 0; p < seg.y; p++) {
        float4 b = g_sorted[r][seg.x + p];
        float dx = q.x - b.x, dy = q.y - b.y, dz = q.z - b.z;
        best2 = fminf(best2, fmaf(dx, dx, fmaf(dy, dy, dz * dz)));
    }
}

// ---------------------------------------------------------------------------
__global__ void init_kernel(float* out) {
    int i = blockIdx.x * blockDim.x + threadIdx.x;
    if (i == 0) {
        *out = 0.0f; g_ovfcnt = 0; g_total[0] = 0; g_total[1] = 0;
        #pragma unroll
        for (int s = 0; s < 2; s++) {
            g_bbox[s][0] = g_bbox[s][1] = g_bbox[s][2] = 0xFFFFFFFFu;
            g_bbox[s][3] = g_bbox[s][4] = g_bbox[s][5] = 0u;
        }
    }
    if (i < NCELL) { g_cnt[0][i] = 0; g_cnt[1][i] = 0; }
}

// ---------------------------------------------------------------------------
__global__ void prep_kernel(const float* __restrict__ tgt,
                            const float* __restrict__ outp, int n, int m) {
    int i = blockIdx.x * blockDim.x + threadIdx.x;
    if (i < n) {
        float x = tgt[3 * i], y = tgt[3 * i + 1], z = tgt[3 * i + 2];
        g_pts[0][i] = make_float4(x, y, z, 0.f);
        atomicMin(&g_bbox[0][0], enc(x)); atomicMax(&g_bbox[0][3], enc(x));
        atomicMin(&g_bbox[0][1], enc(y)); atomicMax(&g_bbox[0][4], enc(y));
        atomicMin(&g_bbox[0][2], enc(z)); atomicMax(&g_bbox[0][5], enc(z));
    }
    if (i < m) {
        float x = outp[3 * i], y = outp[3 * i + 1], z = outp[3 * i + 2];
        g_pts[1][i] = make_float4(x, y, z, 0.f);
        atomicMin(&g_bbox[1][0], enc(x)); atomicMax(&g_bbox[1][3], enc(x));
        atomicMin(&g_bbox[1][1], enc(y)); atomicMax(&g_bbox[1][4], enc(y));
        atomicMin(&g_bbox[1][2], enc(z)); atomicMax(&g_bbox[1][5], enc(z));
    }
}

// ---------------------------------------------------------------------------
__global__ void count_kernel(int n, int m) {
    int i = blockIdx.x * blockDim.x + threadIdx.x;
    #pragma unroll
    for (int s = 0; s < 2; s++) {
        int cnt = (s == 0) ? n : m;
        if (i < cnt) {
            float3 bmin, ih; float hmin;
            grid_params(s, bmin, ih, hmin);
            float4 p = g_pts[s][i];
            int c = (cell_clamp(p.z, bmin.z, ih.z) * GRIDC +
                     cell_clamp(p.y, bmin.y, ih.y)) * GRIDC +
                     cell_clamp(p.x, bmin.x, ih.x);
            g_cellid[s][i] = c;
            atomicAdd(&g_cnt[s][c], 1);
        }
    }
}

// ---------------------------------------------------------------------------
// order-free segment offsets: one atomic per occupied cell (no prefix scan)
__global__ void offsets_kernel() {
    int i = blockIdx.x * blockDim.x + threadIdx.x;
    if (i >= NCELL) return;
    #pragma unroll
    for (int s = 0; s < 2; s++) {
        int cnt = g_cnt[s][i];
        int pos = 0;
        if (cnt > 0) pos = atomicAdd(&g_total[s], cnt);
        g_seg[s][i] = make_int2(pos, cnt);
        g_cursor[s][i] = pos;
    }
}

// ---------------------------------------------------------------------------
__global__ void scatter_kernel(int n, int m) {
    int i = blockIdx.x * blockDim.x + threadIdx.x;
    #pragma unroll
    for (int s = 0; s < 2; s++) {
        int cnt = (s == 0) ? n : m;
        if (i < cnt) {
            int c = g_cellid[s][i];
            int pos = atomicAdd(&g_cursor[s][c], 1);
            g_sorted[s][pos] = g_pts[s][i];
        }
    }
}

// ---------------------------------------------------------------------------
// Phase A: 8 lanes per query, rings 0-1 (27 cells), lane-striped candidates.
__global__ __launch_bounds__(256) void phaseA_kernel(int n, int m) {
    const int lane = threadIdx.x & 31;
    const int sub  = lane & 7;                         // lane within group
    const int total = n + m;
    int gi = blockIdx.x * 32 + (threadIdx.x >> 3);
    const bool valid = (gi < total);
    if (!valid) gi = 0;

    const int s = (gi < n) ? 0 : 1, r = 1 - s;
    const int qi = (s == 0) ? gi : gi - n;
    const float4 q = g_sorted[s][qi];

    float3 bmin, ih; float hmin;
    grid_params(r, bmin, ih, hmin);
    const int cx = cell_clamp(q.x, bmin.x, ih.x);
    const int cy = cell_clamp(q.y, bmin.y, ih.y);
    const int cz = cell_clamp(q.z, bmin.z, ih.z);

    float best2 = 3.4e38f;
    const int zlo = max(cz - 1, 0), zhi = min(cz + 1, GRIDC - 1);
    const int ylo = max(cy - 1, 0), yhi = min(cy + 1, GRIDC - 1);
    const int xlo = max(cx - 1, 0), xhi = min(cx + 1, GRIDC - 1);
    for (int z = zlo; z <= zhi; z++)
        for (int y = ylo; y <= yhi; y++) {
            int rowbase = (z * GRIDC + y) * GRIDC;
            for (int x = xlo; x <= xhi; x++) {
                int2 seg = g_seg[r][rowbase + x];
                for (int t = sub; t < seg.y; t += 8) {   // coalesced, 8-way MLP
                    float4 b = g_sorted[r][seg.x + t];
                    float dx = q.x - b.x, dy = q.y - b.y, dz = q.z - b.z;
                    best2 = fminf(best2, fmaf(dx, dx, fmaf(dy, dy, dz * dz)));
                }
            }
        }
    #pragma unroll
    for (int o = 4; o > 0; o >>= 1)
        best2 = fminf(best2, __shfl_xor_sync(0xFFFFFFFFu, best2, o));

    if (valid && sub == 0) {
        g_best2[gi] = best2;
        if (best2 > hmin * hmin) {                      // rings 0-1 not sufficient
            int k = atomicAdd(&g_ovfcnt, 1);
            g_ovf[k] = gi;
        }
    }
}

// ---------------------------------------------------------------------------
// Phase B: warp per unfinished query; lanes cooperatively enumerate shell R.
__global__ __launch_bounds__(256) void phaseB_kernel(int n, int m) {
    const int lane = threadIdx.x & 31;
    const int gwarp = (blockIdx.x * blockDim.x + threadIdx.x) >> 5;
    const int nwarps = (gridDim.x * blockDim.x) >> 5;
    const int ocnt = g_ovfcnt;

    for (int e = gwarp; e < ocnt; e += nwarps) {
        const int gi = g_ovf[e];
        const int s = (gi < n) ? 0 : 1, r = 1 - s;
        const int qi = (s == 0) ? gi : gi - n;
        const float4 q = g_sorted[s][qi];

        float3 bmin, ih; float hmin;
        grid_params(r, bmin, ih, hmin);
        const int cx = cell_clamp(q.x, bmin.x, ih.x);
        const int cy = cell_clamp(q.y, bmin.y, ih.y);
        const int cz = cell_clamp(q.z, bmin.z, ih.z);

        float best2 = g_best2[gi];
        for (int R = 2; R < GRIDC; R++) {
            float lb = (float)(R - 1) * hmin;
            if (best2 <= lb * lb) break;     // exact: unvisited >= (R-1)*hmin
            // caps z = cz ± R: full (2R+1)^2 squares, rows serial, x lane-strided
            for (int zi = 0; zi < 2; zi++) {
                int z = cz + (zi ? R : -R);
                if ((unsigned)z >= GRIDC) continue;
                for (int dy = -R; dy <= R; dy++) {
                    int y = cy + dy;
                    if ((unsigned)y >= GRIDC) continue;
                    int rowbase = (z * GRIDC + y) * GRIDC;
                    for (int x = cx - R + lane; x <= cx + R; x += 32) {
                        if ((unsigned)x >= GRIDC) continue;
                        scan_cell(r, rowbase + x, q, best2);
                    }
                }
            }
            // side rings: z strictly inside; 8R perimeter cells lane-strided
            int twoR = 2 * R;
            for (int z = cz - R + 1; z <= cz + R - 1; z++) {
                if ((unsigned)z >= GRIDC) continue;
                for (int t = lane; t < 4 * twoR; t += 32) {
                    int side = (t >= twoR) + (t >= 2 * twoR) + (t >= 3 * twoR);
                    int u = t - side * twoR;
                    int dy, dx;
                    if      (side == 0) { dy = -R;     dx = -R + u; }
                    else if (side == 1) { dx =  R;     dy = -R + u; }
                    else if (side == 2) { dy =  R;     dx =  R - u; }
                    else                { dx = -R;     dy =  R - u; }
                    int y = cy + dy, x = cx + dx;
                    if ((unsigned)y >= GRIDC || (unsigned)x >= GRIDC) continue;
                    scan_cell(r, (z * GRIDC + y) * GRIDC + x, q, best2);
                }
            }
            #pragma unroll
            for (int o = 16; o > 0; o >>= 1)
                best2 = fminf(best2, __shfl_xor_sync(0xFFFFFFFFu, best2, o));
        }
        if (lane == 0) g_best2[gi] = best2;
    }
}

// ---------------------------------------------------------------------------
__global__ void reduce_kernel(int n, int m, float* out) {
    __shared__ float warp_sums[8];
    const int total = n + m;
    float sum = 0.0f;
    for (int i = blockIdx.x * blockDim.x + threadIdx.x; i < total;
         i += gridDim.x * blockDim.x)
        sum += sqrtf(g_best2[i]);
    #pragma unroll
    for (int o = 16; o > 0; o >>= 1)
        sum += __shfl_down_sync(0xFFFFFFFFu, sum, o);
    int lane = threadIdx.x & 31, wid = threadIdx.x >> 5;
    if (lane == 0) warp_sums[wid] = sum;
    __syncthreads();
    if (wid == 0) {
        sum = (lane < 8) ? warp_sums[lane] : 0.0f;
        #pragma unroll
        for (int o = 4; o > 0; o >>= 1)
            sum += __shfl_down_sync(0xFFFFFFFFu, sum, o);
        if (lane == 0) atomicAdd(out, sum * 1.0e-3f);
    }
}

// ---------------------------------------------------------------------------
extern "C" void kernel_launch(void* const* d_in, const int* in_sizes, int n_in,
                              void* d_out, int out_size) {
    const float* target = (const float*)d_in[0];
    const float* output = (const float*)d_in[1];
    const int n = in_sizes[0] / 3;
    const int m = in_sizes[1] / 3;
    float* out = (float*)d_out;

    int pmax = max(n, m);
    int total = n + m;
    init_kernel<<<(NCELL + 255) / 256, 256>>>(out);
    prep_kernel<<<(pmax + 255) / 256, 256>>>(target, output, n, m);
    count_kernel<<<(pmax + 255) / 256, 256>>>(n, m);
    offsets_kernel<<<(NCELL + 255) / 256, 256>>>();
    scatter_kernel<<<(pmax + 255) / 256, 256>>>(n, m);
    phaseA_kernel<<<(total + 31) / 32, 256>>>(n, m);
    phaseB_kernel<<<64, 256>>>(n, m);
    reduce_kernel<<<64, 256>>>(n, m, out);
}